// round 9
// baseline (speedup 1.0000x reference)
#include <cuda_runtime.h>
#include <cstdint>

#define BATCH 8
#define HEADS 8
#define NSEQ  4096
#define DM    512
#define DH    64
#define RP    256
#define MTOT  (BATCH*NSEQ)

__device__ float g_wc[4*DM*DM];               // tf32(wq,wk,wv,wo)
__device__ float g_Q [BATCH*HEADS*NSEQ*DH];
__device__ float g_K [BATCH*HEADS*NSEQ*DH];
__device__ float g_V [BATCH*HEADS*NSEQ*DH];
__device__ float g_KP[BATCH*HEADS*RP*DH];
__device__ float g_VP[BATCH*HEADS*RP*DH];
__device__ float g_AO[BATCH*NSEQ*DM];

// ---------------- helpers ----------------
__device__ __forceinline__ float f2tf(float f) {
    unsigned u; asm("cvt.rna.tf32.f32 %0, %1;" : "=r"(u) : "f"(f));
    return __uint_as_float(u);
}
__device__ __forceinline__ float4 cvt4(float4 v) {
    return make_float4(f2tf(v.x), f2tf(v.y), f2tf(v.z), f2tf(v.w));
}
__device__ __forceinline__ void mma_tf32(float c[4], float a0, float a1, float a2, float a3,
                                         float b0, float b1) {
    asm volatile(
        "mma.sync.aligned.m16n8k8.row.col.f32.tf32.tf32.f32 "
        "{%0,%1,%2,%3},{%4,%5,%6,%7},{%8,%9},{%0,%1,%2,%3};\n"
        : "+f"(c[0]), "+f"(c[1]), "+f"(c[2]), "+f"(c[3])
        : "r"(__float_as_uint(a0)), "r"(__float_as_uint(a1)),
          "r"(__float_as_uint(a2)), "r"(__float_as_uint(a3)),
          "r"(__float_as_uint(b0)), "r"(__float_as_uint(b1)));
}
__device__ __forceinline__ uint32_t s2u(const void* p) {
    return (uint32_t)__cvta_generic_to_shared(p);
}
__device__ __forceinline__ void cpa16(uint32_t dst, const void* src) {
    asm volatile("cp.async.cg.shared.global [%0], [%1], 16;\n" :: "r"(dst), "l"(src));
}
__device__ __forceinline__ void cpcommit() {
    asm volatile("cp.async.commit_group;\n" ::: "memory");
}
template<int N> __device__ __forceinline__ void cpwait() {
    asm volatile("cp.async.wait_group %0;\n" :: "n"(N) : "memory");
}

__global__ void cvtk(const float* __restrict__ s, float* __restrict__ d, int n) {
    int i = (blockIdx.x * 256 + threadIdx.x) * 4;
    if (i >= n) return;
    *(float4*)(d + i) = cvt4(*(const float4*)(s + i));
}

// =====================================================================
// gemm_k: C[m][c] = sum_k A[m][k] w[k][c].  BM=128 BN=64 BK=32,
// 2-stage cp.async, 3 CTAs/SM, warp tile 32x32 (8 warps = 4m x 2n).
// A raw f32 (f2tf at fragment), B pre-converted tf32 (no cvt in loop).
// MODE 0: qkv (z selects w + head-split dest), MODE 1: outproj (+bias).
// =====================================================================
#define GA (128*36)
#define GB (32*72)
#define GSTG (GA+GB)
#define G_SMEM (2*GSTG*4)

template<int MODE>
__global__ __launch_bounds__(256, 3) void gemm_k(
    const float* __restrict__ Asrc, const float* __restrict__ bo,
    float* __restrict__ out)
{
    extern __shared__ float sm[];
    const float* w = g_wc + (MODE == 0 ? blockIdx.z : 3) * DM * DM;

    const int m0 = blockIdx.y * 128, n0 = blockIdx.x * 64;
    const int tid = threadIdx.x;
    const int wid = tid >> 5, lane = tid & 31, g = lane >> 2, tig = lane & 3;
    const int wm = (wid >> 1) * 32, wn = (wid & 1) * 32;

    float acc[2][4][4] = {};

    auto load = [&](int s) {
        float* buf = sm + (s & 1) * GSTG;
        const int k0 = s * 32;
        const uint32_t ab = s2u(buf), bb = s2u(buf + GA);
        #pragma unroll
        for (int l = 0; l < 4; l++) {
            int r = l * 32 + (tid >> 3), c = (tid & 7) * 4;
            cpa16(ab + (r * 36 + c) * 4, &Asrc[(m0 + r) * DM + k0 + c]);
        }
        #pragma unroll
        for (int l = 0; l < 2; l++) {
            int r = l * 16 + (tid >> 4), c = (tid & 15) * 4;
            cpa16(bb + (r * 72 + c) * 4, &w[(k0 + r) * DM + n0 + c]);
        }
        cpcommit();
    };

    load(0);
    for (int s = 0; s < 16; s++) {
        if (s + 1 < 16) { load(s + 1); cpwait<1>(); }
        else { cpwait<0>(); }
        __syncthreads();

        const float* A = sm + (s & 1) * GSTG;
        const float* B = A + GA;
        #pragma unroll
        for (int ks = 0; ks < 4; ks++) {
            int kb = ks * 8;
            float a[2][4];
            #pragma unroll
            for (int mt = 0; mt < 2; mt++) {
                int r = wm + mt * 16;
                a[mt][0] = f2tf(A[(r + g)     * 36 + kb + tig]);
                a[mt][1] = f2tf(A[(r + g + 8) * 36 + kb + tig]);
                a[mt][2] = f2tf(A[(r + g)     * 36 + kb + tig + 4]);
                a[mt][3] = f2tf(A[(r + g + 8) * 36 + kb + tig + 4]);
            }
            #pragma unroll
            for (int nt = 0; nt < 4; nt++) {
                float b0 = B[(kb + tig)     * 72 + wn + nt * 8 + g];
                float b1 = B[(kb + tig + 4) * 72 + wn + nt * 8 + g];
                #pragma unroll
                for (int mt = 0; mt < 2; mt++)
                    mma_tf32(acc[mt][nt], a[mt][0], a[mt][1], a[mt][2], a[mt][3], b0, b1);
            }
        }
        __syncthreads();
    }

    #pragma unroll
    for (int mt = 0; mt < 2; mt++) {
        #pragma unroll
        for (int i = 0; i < 2; i++) {
            int m = m0 + wm + mt * 16 + g + i * 8;
            #pragma unroll
            for (int nt = 0; nt < 4; nt++) {
                int c = n0 + wn + nt * 8 + tig * 2;
                float v0 = acc[mt][nt][i * 2], v1 = acc[mt][nt][i * 2 + 1];
                if (MODE == 0) {
                    float* outp = (blockIdx.z == 0) ? g_Q : (blockIdx.z == 1) ? g_K : g_V;
                    int bb2 = m >> 12, ns = m & (NSEQ - 1), h = c >> 6, dh = c & 63;
                    *(float2*)&outp[((bb2 * HEADS + h) * NSEQ + ns) * DH + dh] =
                        make_float2(v0, v1);
                } else {
                    float2 bias = *(const float2*)&bo[c];
                    *(float2*)&out[m * DM + c] = make_float2(v0 + bias.x, v1 + bias.y);
                }
            }
        }
    }
}

// =====================================================================
// proj: KP[r,d] = sum_n E[n,r] K[n,d] per (bh).  BM=128 BN=64 BK=32,
// 2-stage, 3 CTAs/SM.  f2tf at fragment load (round-7 arithmetic).
// =====================================================================
#define PA (32*136)
#define PB (32*72)
#define PSTG (PA+PB)
#define P_SMEM (2*PSTG*4)

__global__ __launch_bounds__(256, 3) void proj_kernel(
    const float* __restrict__ E, const float* __restrict__ F)
{
    extern __shared__ float sm[];

    const int bh = blockIdx.y, h = bh & 7;
    const int r0 = blockIdx.x * 128;
    const float* P = (blockIdx.z == 0 ? E : F) + h * NSEQ * RP;
    const float* S = (blockIdx.z == 0 ? g_K : g_V) + bh * NSEQ * DH;
    float*       D = (blockIdx.z == 0 ? g_KP : g_VP) + bh * RP * DH;

    const int tid = threadIdx.x;
    const int wid = tid >> 5, lane = tid & 31, g = lane >> 2, tig = lane & 3;
    const int wm = (wid >> 1) * 32, wn = (wid & 1) * 32;

    float acc[2][4][4] = {};

    auto load = [&](int s) {
        float* buf = sm + (s & 1) * PSTG;
        const int k0 = s * 32;
        const uint32_t ab = s2u(buf), bb = s2u(buf + PA);
        #pragma unroll
        for (int l = 0; l < 4; l++) {
            int r = l * 8 + (tid >> 5), c = (tid & 31) * 4;
            cpa16(ab + (r * 136 + c) * 4, &P[(k0 + r) * RP + r0 + c]);
        }
        #pragma unroll
        for (int l = 0; l < 2; l++) {
            int r = l * 16 + (tid >> 4), c = (tid & 15) * 4;
            cpa16(bb + (r * 72 + c) * 4, &S[(k0 + r) * DH + c]);
        }
        cpcommit();
    };

    const int NST = NSEQ / 32;
    load(0);
    for (int s = 0; s < NST; s++) {
        if (s + 1 < NST) { load(s + 1); cpwait<1>(); }
        else { cpwait<0>(); }
        __syncthreads();

        const float* A = sm + (s & 1) * PSTG;
        const float* B = A + PA;
        #pragma unroll
        for (int ks = 0; ks < 4; ks++) {
            int kb = ks * 8;
            float a[2][4];
            #pragma unroll
            for (int mt = 0; mt < 2; mt++) {
                int r = wm + mt * 16;
                a[mt][0] = f2tf(A[(kb + tig)     * 136 + r + g]);
                a[mt][1] = f2tf(A[(kb + tig)     * 136 + r + g + 8]);
                a[mt][2] = f2tf(A[(kb + tig + 4) * 136 + r + g]);
                a[mt][3] = f2tf(A[(kb + tig + 4) * 136 + r + g + 8]);
            }
            #pragma unroll
            for (int nt = 0; nt < 4; nt++) {
                float b0 = f2tf(B[(kb + tig)     * 72 + wn + nt * 8 + g]);
                float b1 = f2tf(B[(kb + tig + 4) * 72 + wn + nt * 8 + g]);
                #pragma unroll
                for (int mt = 0; mt < 2; mt++)
                    mma_tf32(acc[mt][nt], a[mt][0], a[mt][1], a[mt][2], a[mt][3], b0, b1);
            }
        }
        __syncthreads();
    }

    #pragma unroll
    for (int mt = 0; mt < 2; mt++) {
        #pragma unroll
        for (int i = 0; i < 2; i++) {
            int r = r0 + wm + mt * 16 + g + i * 8;
            #pragma unroll
            for (int nt = 0; nt < 4; nt++) {
                int c = wn + nt * 8 + tig * 2;
                *(float2*)&D[r * DH + c] =
                    make_float2(acc[mt][nt][i * 2], acc[mt][nt][i * 2 + 1]);
            }
        }
    }
}

// =====================================================================
// attn: round-7 verbatim.  grid (16, 64), 4 chunks of 64 Q rows.
// =====================================================================
#define AT_QS (64*68)
#define AT_KP (256*68)
#define AT_VP (256*72)
#define AT_PS (64*260)
#define AT_SMEM ((AT_QS + AT_KP + AT_VP + AT_PS + 256 + 64)*4)

__global__ __launch_bounds__(256) void attn_kernel()
{
    extern __shared__ float sm[];
    float* Qs   = sm;
    float* kps  = Qs + AT_QS;
    float* vps  = kps + AT_KP;
    float* Ps   = vps + AT_VP;
    float* redM = Ps + AT_PS;
    float* redS = redM + 128;

    const int bh = blockIdx.y;
    const float* kp = g_KP + bh * RP * DH;
    const float* vp = g_VP + bh * RP * DH;

    const int tid = threadIdx.x;
    const int wid = tid >> 5, lane = tid & 31, g = lane >> 2, tig = lane & 3;
    const int wm = (wid >> 1) * 16, wn = wid & 1;

    #pragma unroll
    for (int l = 0; l < 16; l++) {
        int idx = l * 256 + tid;
        int r = idx >> 4, c = (idx & 15) * 4;
        *(float4*)&kps[r * 68 + c] = cvt4(*(const float4*)&kp[r * DH + c]);
        *(float4*)&vps[r * 72 + c] = cvt4(*(const float4*)&vp[r * DH + c]);
    }

    const int b = bh >> 3, h = bh & 7;
    const float scale = 0.125f;

    for (int ci = 0; ci < 4; ci++) {
        const int n0 = blockIdx.x * 256 + ci * 64;
        const float* Qg = g_Q + (bh * NSEQ + n0) * DH;

        __syncthreads();
        #pragma unroll
        for (int l = 0; l < 4; l++) {
            int idx = l * 256 + tid;
            int r = idx >> 4, c = (idx & 15) * 4;
            *(float4*)&Qs[r * 68 + c] = cvt4(*(const float4*)&Qg[r * DH + c]);
        }
        __syncthreads();

        float acc[16][4] = {};
        #pragma unroll
        for (int ks = 0; ks < 8; ks++) {
            int kb = ks * 8;
            float a0 = Qs[(wm + g)     * 68 + kb + tig];
            float a1 = Qs[(wm + g + 8) * 68 + kb + tig];
            float a2 = Qs[(wm + g)     * 68 + kb + tig + 4];
            float a3 = Qs[(wm + g + 8) * 68 + kb + tig + 4];
            #pragma unroll
            for (int nt = 0; nt < 16; nt++) {
                int rr = wn * 128 + nt * 8 + g;
                float b0 = kps[rr * 68 + kb + tig];
                float b1 = kps[rr * 68 + kb + tig + 4];
                mma_tf32(acc[nt], a0, a1, a2, a3, b0, b1);
            }
        }

        const int r0 = wm + g, r1 = r0 + 8;
        float mx0 = -1e30f, mx1 = -1e30f;
        #pragma unroll
        for (int nt = 0; nt < 16; nt++) {
            mx0 = fmaxf(mx0, fmaxf(acc[nt][0], acc[nt][1]));
            mx1 = fmaxf(mx1, fmaxf(acc[nt][2], acc[nt][3]));
        }
        mx0 = fmaxf(mx0, __shfl_xor_sync(0xffffffffu, mx0, 1));
        mx0 = fmaxf(mx0, __shfl_xor_sync(0xffffffffu, mx0, 2));
        mx1 = fmaxf(mx1, __shfl_xor_sync(0xffffffffu, mx1, 1));
        mx1 = fmaxf(mx1, __shfl_xor_sync(0xffffffffu, mx1, 2));
        if (tig == 0) { redM[r0 * 2 + wn] = mx0; redM[r1 * 2 + wn] = mx1; }
        __syncthreads();
        mx0 = fmaxf(redM[r0 * 2], redM[r0 * 2 + 1]) * scale;
        mx1 = fmaxf(redM[r1 * 2], redM[r1 * 2 + 1]) * scale;

        float s0 = 0.f, s1 = 0.f;
        #pragma unroll
        for (int nt = 0; nt < 16; nt++) {
            int c = wn * 128 + nt * 8 + tig * 2;
            float e0 = __expf(acc[nt][0] * scale - mx0);
            float e1 = __expf(acc[nt][1] * scale - mx0);
            s0 += e0 + e1;
            *(float2*)&Ps[r0 * 260 + c] = make_float2(f2tf(e0), f2tf(e1));
            float e2 = __expf(acc[nt][2] * scale - mx1);
            float e3 = __expf(acc[nt][3] * scale - mx1);
            s1 += e2 + e3;
            *(float2*)&Ps[r1 * 260 + c] = make_float2(f2tf(e2), f2tf(e3));
        }
        s0 += __shfl_xor_sync(0xffffffffu, s0, 1);
        s0 += __shfl_xor_sync(0xffffffffu, s0, 2);
        s1 += __shfl_xor_sync(0xffffffffu, s1, 1);
        s1 += __shfl_xor_sync(0xffffffffu, s1, 2);
        if (tig == 0) { redS[r0 * 2 + wn] = s0; redS[r1 * 2 + wn] = s1; }
        __syncthreads();

        float acc2[4][4] = {};
        #pragma unroll 8
        for (int ks = 0; ks < 32; ks++) {
            int kb = ks * 8;
            float a0 = Ps[(wm + g)     * 260 + kb + tig];
            float a1 = Ps[(wm + g + 8) * 260 + kb + tig];
            float a2 = Ps[(wm + g)     * 260 + kb + tig + 4];
            float a3 = Ps[(wm + g + 8) * 260 + kb + tig + 4];
            #pragma unroll
            for (int nt = 0; nt < 4; nt++) {
                int cc = wn * 32 + nt * 8 + g;
                float b0 = vps[(kb + tig)     * 72 + cc];
                float b1 = vps[(kb + tig + 4) * 72 + cc];
                mma_tf32(acc2[nt], a0, a1, a2, a3, b0, b1);
            }
        }

        const float inv0 = __frcp_rn(redS[r0 * 2] + redS[r0 * 2 + 1]);
        const float inv1 = __frcp_rn(redS[r1 * 2] + redS[r1 * 2 + 1]);
        float* ao = g_AO + (long)(b * NSEQ + n0) * DM + h * DH;
        #pragma unroll
        for (int nt = 0; nt < 4; nt++) {
            int c = wn * 32 + nt * 8 + tig * 2;
            *(float2*)&ao[r0 * DM + c] = make_float2(acc2[nt][0] * inv0, acc2[nt][1] * inv0);
            *(float2*)&ao[r1 * DM + c] = make_float2(acc2[nt][2] * inv1, acc2[nt][3] * inv1);
        }
    }
}

// =====================================================================
extern "C" void kernel_launch(void* const* d_in, const int* in_sizes, int n_in,
                              void* d_out, int out_size)
{
    (void)in_sizes; (void)n_in; (void)out_size;
    const float* x  = (const float*)d_in[0];
    const float* wq = (const float*)d_in[1];
    const float* wk = (const float*)d_in[2];
    const float* wv = (const float*)d_in[3];
    const float* E  = (const float*)d_in[4];
    const float* F  = (const float*)d_in[5];
    const float* wo = (const float*)d_in[6];
    const float* bo = (const float*)d_in[7];
    float* out = (float*)d_out;

    cudaFuncSetAttribute(gemm_k<0>,  cudaFuncAttributeMaxDynamicSharedMemorySize, G_SMEM);
    cudaFuncSetAttribute(gemm_k<1>,  cudaFuncAttributeMaxDynamicSharedMemorySize, G_SMEM);
    cudaFuncSetAttribute(proj_kernel, cudaFuncAttributeMaxDynamicSharedMemorySize, P_SMEM);
    cudaFuncSetAttribute(attn_kernel, cudaFuncAttributeMaxDynamicSharedMemorySize, AT_SMEM);

    float *p_wc, *p_AO;
    cudaGetSymbolAddress((void**)&p_wc, g_wc);
    cudaGetSymbolAddress((void**)&p_AO, g_AO);

    cvtk<<<DM*DM/1024, 256>>>(wq, p_wc,            DM*DM);
    cvtk<<<DM*DM/1024, 256>>>(wk, p_wc + DM*DM,    DM*DM);
    cvtk<<<DM*DM/1024, 256>>>(wv, p_wc + 2*DM*DM,  DM*DM);
    cvtk<<<DM*DM/1024, 256>>>(wo, p_wc + 3*DM*DM,  DM*DM);

    gemm_k<0>  <<<dim3(8, 256, 3), 256, G_SMEM>>>(x, nullptr, nullptr);
    proj_kernel<<<dim3(2, 64, 2),  256, P_SMEM>>>(E, F);
    attn_kernel<<<dim3(16, 64),    256, AT_SMEM>>>();
    gemm_k<1>  <<<dim3(8, 256, 1), 256, G_SMEM>>>(p_AO, bo, out);
}

// round 10
// speedup vs baseline: 1.1290x; 1.1290x over previous
#include <cuda_runtime.h>
#include <cstdint>

#define BATCH 8
#define HEADS 8
#define NSEQ  4096
#define DM    512
#define DH    64
#define RP    256
#define MTOT  (BATCH*NSEQ)

// packed-A layout: quad q=((tm*nkt+tk)*32 + g*4+tig); elems (e)=(m0+g+8hm, k0+tig+4hk), e=hm+2hk
// packed-B layout: pair q=((tn*nkt+tk)*32 + g*4+tig); elems (e)=(c0+g, k0+tig+4e)
__device__ float g_xp[MTOT*DM];          // packed-A tf32(x)
__device__ float g_wp[4*DM*DM];          // packed-B tf32(wq,wk,wv,wo)
__device__ float g_Ep[HEADS*RP*NSEQ];    // packed-A tf32(E^T), per head M=256 K=4096
__device__ float g_Fp[HEADS*RP*NSEQ];
__device__ float g_Q [MTOT*DM];          // raw f32 [bh][n][64]
__device__ float g_K [MTOT*DM];          // tf32 vals [bh][n][64]
__device__ float g_V [MTOT*DM];
__device__ float g_KP[64*RP*DH];
__device__ float g_VP[64*RP*DH];
__device__ float g_AO[MTOT*DM];          // tf32 vals [m][512]

// ---------------- helpers ----------------
__device__ __forceinline__ float f2tf(float f) {
    unsigned u; asm("cvt.rna.tf32.f32 %0, %1;" : "=r"(u) : "f"(f));
    return __uint_as_float(u);
}
__device__ __forceinline__ float4 cvt4(float4 v) {
    return make_float4(f2tf(v.x), f2tf(v.y), f2tf(v.z), f2tf(v.w));
}
__device__ __forceinline__ void mma_tf32(float c[4], float a0, float a1, float a2, float a3,
                                         float b0, float b1) {
    asm volatile(
        "mma.sync.aligned.m16n8k8.row.col.f32.tf32.tf32.f32 "
        "{%0,%1,%2,%3},{%4,%5,%6,%7},{%8,%9},{%0,%1,%2,%3};\n"
        : "+f"(c[0]), "+f"(c[1]), "+f"(c[2]), "+f"(c[3])
        : "r"(__float_as_uint(a0)), "r"(__float_as_uint(a1)),
          "r"(__float_as_uint(a2)), "r"(__float_as_uint(a3)),
          "r"(__float_as_uint(b0)), "r"(__float_as_uint(b1)));
}
__device__ __forceinline__ uint32_t s2u(const void* p) {
    return (uint32_t)__cvta_generic_to_shared(p);
}
__device__ __forceinline__ void cpa16(uint32_t dst, const void* src) {
    asm volatile("cp.async.cg.shared.global [%0], [%1], 16;\n" :: "r"(dst), "l"(src));
}
__device__ __forceinline__ void cpcommit() {
    asm volatile("cp.async.commit_group;\n" ::: "memory");
}
template<int N> __device__ __forceinline__ void cpwait() {
    asm volatile("cp.async.wait_group %0;\n" :: "n"(N) : "memory");
}

// ---------------- pack kernels ----------------
__global__ void pack_a(const float* __restrict__ s, float* __restrict__ d,
                       int nkt, int sm, int sk, long sS, long dS) {
    s += blockIdx.y * sS; d += blockIdx.y * dS;
    int q = blockIdx.x * 256 + threadIdx.x;
    int tile = q >> 5, lane = q & 31;
    int tm = tile / nkt, tk = tile - tm * nkt;
    const float* p = s + (long)(tm * 16 + (lane >> 2)) * sm + (long)(tk * 8 + (lane & 3)) * sk;
    float4 v = make_float4(f2tf(p[0]), f2tf(p[8 * sm]), f2tf(p[4 * sk]), f2tf(p[8 * sm + 4 * sk]));
    *(float4*)(d + (long)q * 4) = v;
}
__global__ void pack_b(const float* __restrict__ s, float* __restrict__ d, int nkt, int sk) {
    int q = blockIdx.x * 256 + threadIdx.x;
    int tile = q >> 5, lane = q & 31;
    int tn = tile / nkt, tk = tile - tn * nkt;
    const float* p = s + (long)(tk * 8 + (lane & 3)) * sk + tn * 8 + (lane >> 2);
    *(float2*)(d + (long)q * 2) = make_float2(f2tf(p[0]), f2tf(p[4 * sk]));
}

// =====================================================================
// qkv: C = x @ w (z = q/k/v).  BM=BN=128, BK=32, 3-stage, packed A+B.
// Inner loop: 2 LDS.128 + 8 LDS.64 + 16 HMMA per k8 per warp.
// K,V written pre-tf32; Q raw.
// =====================================================================
#define QSTG 8192
#define QKV_SMEM (3*QSTG*4)

__global__ __launch_bounds__(256, 2) void qkv_kernel()
{
    extern __shared__ float sm[];
    const float* wsrc = g_wp + blockIdx.z * DM * DM;
    float* outp = (blockIdx.z == 0) ? g_Q : (blockIdx.z == 1) ? g_K : g_V;

    const int m0t = blockIdx.y * 8;   // A tile base (16-row tiles)
    const int n0t = blockIdx.x * 16;  // B tile base (8-col tiles)
    const int tid = threadIdx.x, wid = tid >> 5, lane = tid & 31;
    const int g = lane >> 2, tig = lane & 3;
    const int tmB = (wid >> 1) * 2, tnB = (wid & 1) * 8;

    float acc[2][8][4] = {};

    auto load = [&](int s) {
        float* buf = sm + (s % 3) * QSTG;
        uint32_t ab = s2u(buf), bb = s2u(buf + 4096);
        #pragma unroll
        for (int l = 0; l < 4; l++) {
            int q = l * 256 + tid, tl = q >> 7, r = q & 127;
            cpa16(ab + (tl * 512 + r * 4) * 4, &g_xp[(long)(m0t + tl) * 8192 + s * 512 + r * 4]);
        }
        #pragma unroll
        for (int l = 0; l < 4; l++) {
            int q = l * 256 + tid, tl = q >> 6, r = q & 63;
            cpa16(bb + (tl * 256 + r * 4) * 4, &wsrc[(long)(n0t + tl) * 4096 + s * 256 + r * 4]);
        }
        cpcommit();
    };

    load(0); load(1);
    for (int s = 0; s < 16; s++) {
        if (s + 2 < 16) { load(s + 2); cpwait<2>(); }
        else if (s + 1 < 16) { cpwait<1>(); }
        else { cpwait<0>(); }
        __syncthreads();

        const float* A = sm + (s % 3) * QSTG;
        const float* B = A + 4096;
        #pragma unroll
        for (int ks = 0; ks < 4; ks++) {
            float4 a0 = *(const float4*)&A[((tmB    ) * 4 + ks) * 128 + lane * 4];
            float4 a1 = *(const float4*)&A[((tmB + 1) * 4 + ks) * 128 + lane * 4];
            #pragma unroll
            for (int nt = 0; nt < 8; nt++) {
                float2 bv = *(const float2*)&B[((tnB + nt) * 4 + ks) * 64 + lane * 2];
                mma_tf32(acc[0][nt], a0.x, a0.y, a0.z, a0.w, bv.x, bv.y);
                mma_tf32(acc[1][nt], a1.x, a1.y, a1.z, a1.w, bv.x, bv.y);
            }
        }
        __syncthreads();
    }

    const bool cv = (blockIdx.z != 0);
    #pragma unroll
    for (int mt = 0; mt < 2; mt++)
    #pragma unroll
    for (int i = 0; i < 2; i++) {
        int m = m0t * 16 + (tmB + mt) * 16 + g + i * 8;
        int bb2 = m >> 12, ns = m & (NSEQ - 1);
        #pragma unroll
        for (int nt = 0; nt < 8; nt++) {
            int c = n0t * 8 + (tnB + nt) * 8 + tig * 2;
            int h = c >> 6, dh = c & 63;
            float v0 = acc[mt][nt][i * 2], v1 = acc[mt][nt][i * 2 + 1];
            if (cv) { v0 = f2tf(v0); v1 = f2tf(v1); }
            *(float2*)&outp[((long)(bb2 * HEADS + h) * NSEQ + ns) * DH + dh] = make_float2(v0, v1);
        }
    }
}

// =====================================================================
// proj: KP[r,d] = sum_n E[n,r] K[n,d] per (bh,z).  BM=128 BN=64 BK=32.
// A packed (E/F); B raw [k][72] from pre-tf32 K/V (no cvt in loop).
// =====================================================================
#define PSTG (4096 + 32*72)
#define PRJ_SMEM (3*PSTG*4)

__global__ __launch_bounds__(256, 2) void proj_kernel()
{
    extern __shared__ float sm[];
    const int bh = blockIdx.y, h = bh & 7;
    const int r0t = blockIdx.x * 8;
    const float* Ap = (blockIdx.z == 0 ? g_Ep : g_Fp) + (long)h * RP * NSEQ;
    const float* S  = (blockIdx.z == 0 ? g_K : g_V) + (long)bh * NSEQ * DH;
    float* D = (blockIdx.z == 0 ? g_KP : g_VP) + bh * RP * DH;

    const int tid = threadIdx.x, wid = tid >> 5, lane = tid & 31;
    const int g = lane >> 2, tig = lane & 3;
    const int tmB = (wid >> 1) * 2, wn = (wid & 1) * 32;

    float acc[2][4][4] = {};

    auto load = [&](int s) {
        float* buf = sm + (s % 3) * PSTG;
        uint32_t ab = s2u(buf), bb = s2u(buf + 4096);
        #pragma unroll
        for (int l = 0; l < 4; l++) {
            int q = l * 256 + tid, tl = q >> 7, r = q & 127;
            cpa16(ab + (tl * 512 + r * 4) * 4, &Ap[(long)(r0t + tl) * 65536 + s * 512 + r * 4]);
        }
        #pragma unroll
        for (int l = 0; l < 2; l++) {
            int rr = l * 16 + (tid >> 4), c4 = (tid & 15) * 4;
            cpa16(bb + (rr * 72 + c4) * 4, &S[(long)(s * 32 + rr) * DH + c4]);
        }
        cpcommit();
    };

    load(0); load(1);
    for (int s = 0; s < 128; s++) {
        if (s + 2 < 128) { load(s + 2); cpwait<2>(); }
        else if (s + 1 < 128) { cpwait<1>(); }
        else { cpwait<0>(); }
        __syncthreads();

        const float* A = sm + (s % 3) * PSTG;
        const float* B = A + 4096;
        #pragma unroll
        for (int ks = 0; ks < 4; ks++) {
            int kb = ks * 8;
            float4 a0 = *(const float4*)&A[((tmB    ) * 4 + ks) * 128 + lane * 4];
            float4 a1 = *(const float4*)&A[((tmB + 1) * 4 + ks) * 128 + lane * 4];
            #pragma unroll
            for (int nt = 0; nt < 4; nt++) {
                float b0 = B[(kb + tig)     * 72 + wn + nt * 8 + g];
                float b1 = B[(kb + tig + 4) * 72 + wn + nt * 8 + g];
                mma_tf32(acc[0][nt], a0.x, a0.y, a0.z, a0.w, b0, b1);
                mma_tf32(acc[1][nt], a1.x, a1.y, a1.z, a1.w, b0, b1);
            }
        }
        __syncthreads();
    }

    #pragma unroll
    for (int mt = 0; mt < 2; mt++)
    #pragma unroll
    for (int i = 0; i < 2; i++) {
        int r = r0t * 16 + (tmB + mt) * 16 + g + i * 8;
        #pragma unroll
        for (int nt = 0; nt < 4; nt++) {
            int c = wn + nt * 8 + tig * 2;
            *(float2*)&D[r * DH + c] = make_float2(acc[mt][nt][i * 2], acc[mt][nt][i * 2 + 1]);
        }
    }
}

// =====================================================================
// attn: round-7 verbatim; AO stored pre-tf32 (R8-proven bit-safe).
// =====================================================================
#define AT_QS (64*68)
#define AT_KP (256*68)
#define AT_VP (256*72)
#define AT_PS (64*260)
#define AT_SMEM ((AT_QS + AT_KP + AT_VP + AT_PS + 256 + 64)*4)

__global__ __launch_bounds__(256) void attn_kernel()
{
    extern __shared__ float sm[];
    float* Qs   = sm;
    float* kps  = Qs + AT_QS;
    float* vps  = kps + AT_KP;
    float* Ps   = vps + AT_VP;
    float* redM = Ps + AT_PS;
    float* redS = redM + 128;

    const int bh = blockIdx.y;
    const float* kp = g_KP + bh * RP * DH;
    const float* vp = g_VP + bh * RP * DH;

    const int tid = threadIdx.x;
    const int wid = tid >> 5, lane = tid & 31, g = lane >> 2, tig = lane & 3;
    const int wm = (wid >> 1) * 16, wn = wid & 1;

    #pragma unroll
    for (int l = 0; l < 16; l++) {
        int idx = l * 256 + tid;
        int r = idx >> 4, c = (idx & 15) * 4;
        *(float4*)&kps[r * 68 + c] = cvt4(*(const float4*)&kp[r * DH + c]);
        *(float4*)&vps[r * 72 + c] = cvt4(*(const float4*)&vp[r * DH + c]);
    }

    const int b = bh >> 3, h = bh & 7;
    const float scale = 0.125f;

    for (int ci = 0; ci < 4; ci++) {
        const int n0 = blockIdx.x * 256 + ci * 64;
        const float* Qg = g_Q + (long)(bh * NSEQ + n0) * DH;

        __syncthreads();
        #pragma unroll
        for (int l = 0; l < 4; l++) {
            int idx = l * 256 + tid;
            int r = idx >> 4, c = (idx & 15) * 4;
            *(float4*)&Qs[r * 68 + c] = cvt4(*(const float4*)&Qg[r * DH + c]);
        }
        __syncthreads();

        float acc[16][4] = {};
        #pragma unroll
        for (int ks = 0; ks < 8; ks++) {
            int kb = ks * 8;
            float a0 = Qs[(wm + g)     * 68 + kb + tig];
            float a1 = Qs[(wm + g + 8) * 68 + kb + tig];
            float a2 = Qs[(wm + g)     * 68 + kb + tig + 4];
            float a3 = Qs[(wm + g + 8) * 68 + kb + tig + 4];
            #pragma unroll
            for (int nt = 0; nt < 16; nt++) {
                int rr = wn * 128 + nt * 8 + g;
                float b0 = kps[rr * 68 + kb + tig];
                float b1 = kps[rr * 68 + kb + tig + 4];
                mma_tf32(acc[nt], a0, a1, a2, a3, b0, b1);
            }
        }

        const int r0 = wm + g, r1 = r0 + 8;
        float mx0 = -1e30f, mx1 = -1e30f;
        #pragma unroll
        for (int nt = 0; nt < 16; nt++) {
            mx0 = fmaxf(mx0, fmaxf(acc[nt][0], acc[nt][1]));
            mx1 = fmaxf(mx1, fmaxf(acc[nt][2], acc[nt][3]));
        }
        mx0 = fmaxf(mx0, __shfl_xor_sync(0xffffffffu, mx0, 1));
        mx0 = fmaxf(mx0, __shfl_xor_sync(0xffffffffu, mx0, 2));
        mx1 = fmaxf(mx1, __shfl_xor_sync(0xffffffffu, mx1, 1));
        mx1 = fmaxf(mx1, __shfl_xor_sync(0xffffffffu, mx1, 2));
        if (tig == 0) { redM[r0 * 2 + wn] = mx0; redM[r1 * 2 + wn] = mx1; }
        __syncthreads();
        mx0 = fmaxf(redM[r0 * 2], redM[r0 * 2 + 1]) * scale;
        mx1 = fmaxf(redM[r1 * 2], redM[r1 * 2 + 1]) * scale;

        float s0 = 0.f, s1 = 0.f;
        #pragma unroll
        for (int nt = 0; nt < 16; nt++) {
            int c = wn * 128 + nt * 8 + tig * 2;
            float e0 = __expf(acc[nt][0] * scale - mx0);
            float e1 = __expf(acc[nt][1] * scale - mx0);
            s0 += e0 + e1;
            *(float2*)&Ps[r0 * 260 + c] = make_float2(f2tf(e0), f2tf(e1));
            float e2 = __expf(acc[nt][2] * scale - mx1);
            float e3 = __expf(acc[nt][3] * scale - mx1);
            s1 += e2 + e3;
            *(float2*)&Ps[r1 * 260 + c] = make_float2(f2tf(e2), f2tf(e3));
        }
        s0 += __shfl_xor_sync(0xffffffffu, s0, 1);
        s0 += __shfl_xor_sync(0xffffffffu, s0, 2);
        s1 += __shfl_xor_sync(0xffffffffu, s1, 1);
        s1 += __shfl_xor_sync(0xffffffffu, s1, 2);
        if (tig == 0) { redS[r0 * 2 + wn] = s0; redS[r1 * 2 + wn] = s1; }
        __syncthreads();

        float acc2[4][4] = {};
        #pragma unroll 8
        for (int ks = 0; ks < 32; ks++) {
            int kb = ks * 8;
            float a0 = Ps[(wm + g)     * 260 + kb + tig];
            float a1 = Ps[(wm + g + 8) * 260 + kb + tig];
            float a2 = Ps[(wm + g)     * 260 + kb + tig + 4];
            float a3 = Ps[(wm + g + 8) * 260 + kb + tig + 4];
            #pragma unroll
            for (int nt = 0; nt < 4; nt++) {
                int cc = wn * 32 + nt * 8 + g;
                float b0 = vps[(kb + tig)     * 72 + cc];
                float b1 = vps[(kb + tig + 4) * 72 + cc];
                mma_tf32(acc2[nt], a0, a1, a2, a3, b0, b1);
            }
        }

        const float inv0 = __frcp_rn(redS[r0 * 2] + redS[r0 * 2 + 1]);
        const float inv1 = __frcp_rn(redS[r1 * 2] + redS[r1 * 2 + 1]);
        float* ao = g_AO + (long)(b * NSEQ + n0) * DM + h * DH;
        #pragma unroll
        for (int nt = 0; nt < 4; nt++) {
            int c = wn * 32 + nt * 8 + tig * 2;
            *(float2*)&ao[r0 * DM + c] =
                make_float2(f2tf(acc2[nt][0] * inv0), f2tf(acc2[nt][1] * inv0));
            *(float2*)&ao[r1 * DM + c] =
                make_float2(f2tf(acc2[nt][2] * inv1), f2tf(acc2[nt][3] * inv1));
        }
    }
}

// =====================================================================
// outproj: A raw [128][36] from pre-tf32 AO (no cvt), B packed wo.
// =====================================================================
#define OA 4608
#define OSTG (OA + 4096)
#define OUT_SMEM (3*OSTG*4)

__global__ __launch_bounds__(256, 2) void outproj_kernel(
    const float* __restrict__ bo, float* __restrict__ out)
{
    extern __shared__ float sm[];
    const float* wsrc = g_wp + 3 * DM * DM;

    const int m0 = blockIdx.y * 128, n0t = blockIdx.x * 16;
    const int tid = threadIdx.x, wid = tid >> 5, lane = tid & 31;
    const int g = lane >> 2, tig = lane & 3;
    const int wm = (wid >> 1) * 32, tnB = (wid & 1) * 8;

    float acc[2][8][4] = {};

    auto load = [&](int s) {
        float* buf = sm + (s % 3) * OSTG;
        uint32_t ab = s2u(buf), bb = s2u(buf + OA);
        int k0 = s * 32;
        #pragma unroll
        for (int l = 0; l < 4; l++) {
            int r = l * 32 + (tid >> 3), c4 = (tid & 7) * 4;
            cpa16(ab + (r * 36 + c4) * 4, &g_AO[(long)(m0 + r) * DM + k0 + c4]);
        }
        #pragma unroll
        for (int l = 0; l < 4; l++) {
            int q = l * 256 + tid, tl = q >> 6, r = q & 63;
            cpa16(bb + (tl * 256 + r * 4) * 4, &wsrc[(long)(n0t + tl) * 4096 + s * 256 + r * 4]);
        }
        cpcommit();
    };

    load(0); load(1);
    for (int s = 0; s < 16; s++) {
        if (s + 2 < 16) { load(s + 2); cpwait<2>(); }
        else if (s + 1 < 16) { cpwait<1>(); }
        else { cpwait<0>(); }
        __syncthreads();

        const float* A = sm + (s % 3) * OSTG;
        const float* B = A + OA;
        #pragma unroll
        for (int ks = 0; ks < 4; ks++) {
            int kb = ks * 8;
            float a[2][4];
            #pragma unroll
            for (int mt = 0; mt < 2; mt++) {
                int r = wm + mt * 16;
                a[mt][0] = A[(r + g)     * 36 + kb + tig];
                a[mt][1] = A[(r + g + 8) * 36 + kb + tig];
                a[mt][2] = A[(r + g)     * 36 + kb + tig + 4];
                a[mt][3] = A[(r + g + 8) * 36 + kb + tig + 4];
            }
            #pragma unroll
            for (int nt = 0; nt < 8; nt++) {
                float2 bv = *(const float2*)&B[((tnB + nt) * 4 + ks) * 64 + lane * 2];
                mma_tf32(acc[0][nt], a[0][0], a[0][1], a[0][2], a[0][3], bv.x, bv.y);
                mma_tf32(acc[1][nt], a[1][0], a[1][1], a[1][2], a[1][3], bv.x, bv.y);
            }
        }
        __syncthreads();
    }

    #pragma unroll
    for (int mt = 0; mt < 2; mt++)
    #pragma unroll
    for (int i = 0; i < 2; i++) {
        int m = m0 + wm + mt * 16 + g + i * 8;
        #pragma unroll
        for (int nt = 0; nt < 8; nt++) {
            int c = n0t * 8 + (tnB + nt) * 8 + tig * 2;
            float2 bias = *(const float2*)&bo[c];
            *(float2*)&out[(long)m * DM + c] =
                make_float2(acc[mt][nt][i * 2] + bias.x, acc[mt][nt][i * 2 + 1] + bias.y);
        }
    }
}

// =====================================================================
extern "C" void kernel_launch(void* const* d_in, const int* in_sizes, int n_in,
                              void* d_out, int out_size)
{
    (void)in_sizes; (void)n_in; (void)out_size;
    const float* x  = (const float*)d_in[0];
    const float* wq = (const float*)d_in[1];
    const float* wk = (const float*)d_in[2];
    const float* wv = (const float*)d_in[3];
    const float* E  = (const float*)d_in[4];
    const float* F  = (const float*)d_in[5];
    const float* wo = (const float*)d_in[6];
    const float* bo = (const float*)d_in[7];
    float* out = (float*)d_out;

    cudaFuncSetAttribute(qkv_kernel,     cudaFuncAttributeMaxDynamicSharedMemorySize, QKV_SMEM);
    cudaFuncSetAttribute(proj_kernel,    cudaFuncAttributeMaxDynamicSharedMemorySize, PRJ_SMEM);
    cudaFuncSetAttribute(attn_kernel,    cudaFuncAttributeMaxDynamicSharedMemorySize, AT_SMEM);
    cudaFuncSetAttribute(outproj_kernel, cudaFuncAttributeMaxDynamicSharedMemorySize, OUT_SMEM);

    float *p_xp, *p_wp, *p_Ep, *p_Fp;
    cudaGetSymbolAddress((void**)&p_xp, g_xp);
    cudaGetSymbolAddress((void**)&p_wp, g_wp);
    cudaGetSymbolAddress((void**)&p_Ep, g_Ep);
    cudaGetSymbolAddress((void**)&p_Fp, g_Fp);

    // marshal: x (A-pack, nkt=64), E/F (A-pack per head, M=256 K=4096, nkt=512),
    // weights (B-pack, nkt=64).  All pre-tf32.
    pack_a<<<MTOT*DM/1024, 256>>>(x, p_xp, 64, DM, 1, 0, 0);
    pack_a<<<dim3(RP*NSEQ/1024, HEADS), 256>>>(E, p_Ep, 512, 1, RP,
                                               (long)NSEQ*RP, (long)RP*NSEQ);
    pack_a<<<dim3(RP*NSEQ/1024, HEADS), 256>>>(F, p_Fp, 512, 1, RP,
                                               (long)NSEQ*RP, (long)RP*NSEQ);
    pack_b<<<DM*DM/512, 256>>>(wq, p_wp,            64, DM);
    pack_b<<<DM*DM/512, 256>>>(wk, p_wp + DM*DM,    64, DM);
    pack_b<<<DM*DM/512, 256>>>(wv, p_wp + 2*DM*DM,  64, DM);
    pack_b<<<DM*DM/512, 256>>>(wo, p_wp + 3*DM*DM,  64, DM);

    qkv_kernel    <<<dim3(4, 256, 3), 256, QKV_SMEM>>>();
    proj_kernel   <<<dim3(2, 64, 2),  256, PRJ_SMEM>>>();
    attn_kernel   <<<dim3(16, 64),    256, AT_SMEM>>>();
    outproj_kernel<<<dim3(4, 256),    256, OUT_SMEM>>>(bo, out);
}

// round 11
// speedup vs baseline: 1.1361x; 1.0062x over previous
#include <cuda_runtime.h>
#include <cstdint>

#define BATCH 8
#define HEADS 8
#define NSEQ  4096
#define DM    512
#define DH    64
#define RP    256
#define MTOT  (BATCH*NSEQ)

// packed-A: quad q=((tm*nkt+tk)*32 + g*4+tig); elems e=hm+2hk at (m=16tm+g+8hm, k=8tk+tig+4hk)
// packed-B: pair q=((tn*nkt+tk)*32 + g*4+tig); elems e at (n=8tn+g, k=8tk+tig+4e)
__device__ float g_xp[MTOT*DM];          // packed-A tf32(x)
__device__ float g_wp[4*DM*DM];          // packed-B tf32(wq,wk,wv,wo)
__device__ float g_Ep[HEADS*RP*NSEQ];    // packed-A tf32(E^T) per head
__device__ float g_Fp[HEADS*RP*NSEQ];
__device__ float g_Q [MTOT*DM];          // packed-A tf32 Q per bh (m=n,k=d), nkt=8
__device__ float g_K [MTOT*DM];          // tf32 vals [bh][n][64]
__device__ float g_V [MTOT*DM];
__device__ float g_KP[64*RP*DH];         // packed-B tf32 KP per bh (n=r,k=d), nkt=8
__device__ float g_VP[64*RP*DH];         // packed-B tf32 VP per bh (n=d,k=r), nkt=32
__device__ float g_AO[MTOT*DM];          // tf32 vals [m][512]

// ---------------- helpers ----------------
__device__ __forceinline__ float f2tf(float f) {
    unsigned u; asm("cvt.rna.tf32.f32 %0, %1;" : "=r"(u) : "f"(f));
    return __uint_as_float(u);
}
__device__ __forceinline__ float4 cvt4(float4 v) {
    return make_float4(f2tf(v.x), f2tf(v.y), f2tf(v.z), f2tf(v.w));
}
__device__ __forceinline__ void mma_tf32(float c[4], float a0, float a1, float a2, float a3,
                                         float b0, float b1) {
    asm volatile(
        "mma.sync.aligned.m16n8k8.row.col.f32.tf32.tf32.f32 "
        "{%0,%1,%2,%3},{%4,%5,%6,%7},{%8,%9},{%0,%1,%2,%3};\n"
        : "+f"(c[0]), "+f"(c[1]), "+f"(c[2]), "+f"(c[3])
        : "r"(__float_as_uint(a0)), "r"(__float_as_uint(a1)),
          "r"(__float_as_uint(a2)), "r"(__float_as_uint(a3)),
          "r"(__float_as_uint(b0)), "r"(__float_as_uint(b1)));
}
__device__ __forceinline__ uint32_t s2u(const void* p) {
    return (uint32_t)__cvta_generic_to_shared(p);
}
__device__ __forceinline__ void cpa16(uint32_t dst, const void* src) {
    asm volatile("cp.async.cg.shared.global [%0], [%1], 16;\n" :: "r"(dst), "l"(src));
}
__device__ __forceinline__ void cpcommit() {
    asm volatile("cp.async.commit_group;\n" ::: "memory");
}
template<int N> __device__ __forceinline__ void cpwait() {
    asm volatile("cp.async.wait_group %0;\n" :: "n"(N) : "memory");
}

// ---------------- pack kernels ----------------
__global__ void pack_a(const float* __restrict__ s, float* __restrict__ d,
                       int nkt, int sm, int sk, long sS, long dS) {
    s += blockIdx.y * sS; d += blockIdx.y * dS;
    int q = blockIdx.x * 256 + threadIdx.x;
    int tile = q >> 5, lane = q & 31;
    int tm = tile / nkt, tk = tile - tm * nkt;
    const float* p = s + (long)(tm * 16 + (lane >> 2)) * sm + (long)(tk * 8 + (lane & 3)) * sk;
    float4 v = make_float4(f2tf(p[0]), f2tf(p[8 * sm]), f2tf(p[4 * sk]), f2tf(p[8 * sm + 4 * sk]));
    *(float4*)(d + (long)q * 4) = v;
}
__global__ void pack_b(const float* __restrict__ s, float* __restrict__ d, int nkt, int sk) {
    int q = blockIdx.x * 256 + threadIdx.x;
    int tile = q >> 5, lane = q & 31;
    int tn = tile / nkt, tk = tile - tn * nkt;
    const float* p = s + (long)(tk * 8 + (lane & 3)) * sk + tn * 8 + (lane >> 2);
    *(float2*)(d + (long)q * 2) = make_float2(f2tf(p[0]), f2tf(p[4 * sk]));
}

// =====================================================================
// qkv: C = x @ w (z = q/k/v).  BM=BN=128, BK=32, 3-stage, packed A+B.
// Q written packed-A pre-tf32; K,V head-split pre-tf32.
// =====================================================================
#define QSTG 8192
#define QKV_SMEM (3*QSTG*4)

__global__ __launch_bounds__(256, 2) void qkv_kernel()
{
    extern __shared__ float sm[];
    const float* wsrc = g_wp + blockIdx.z * DM * DM;

    const int m0t = blockIdx.y * 8;
    const int n0t = blockIdx.x * 16;
    const int tid = threadIdx.x, wid = tid >> 5, lane = tid & 31;
    const int g = lane >> 2, tig = lane & 3;
    const int tmB = (wid >> 1) * 2, tnB = (wid & 1) * 8;

    float acc[2][8][4] = {};

    auto load = [&](int s) {
        float* buf = sm + (s % 3) * QSTG;
        uint32_t ab = s2u(buf), bb = s2u(buf + 4096);
        #pragma unroll
        for (int l = 0; l < 4; l++) {
            int q = l * 256 + tid, tl = q >> 7, r = q & 127;
            cpa16(ab + (tl * 512 + r * 4) * 4, &g_xp[(long)(m0t + tl) * 8192 + s * 512 + r * 4]);
        }
        #pragma unroll
        for (int l = 0; l < 4; l++) {
            int q = l * 256 + tid, tl = q >> 6, r = q & 63;
            cpa16(bb + (tl * 256 + r * 4) * 4, &wsrc[(long)(n0t + tl) * 4096 + s * 256 + r * 4]);
        }
        cpcommit();
    };

    load(0); load(1);
    for (int s = 0; s < 16; s++) {
        if (s + 2 < 16) { load(s + 2); cpwait<2>(); }
        else if (s + 1 < 16) { cpwait<1>(); }
        else { cpwait<0>(); }
        __syncthreads();

        const float* A = sm + (s % 3) * QSTG;
        const float* B = A + 4096;
        #pragma unroll
        for (int ks = 0; ks < 4; ks++) {
            float4 a0 = *(const float4*)&A[((tmB    ) * 4 + ks) * 128 + lane * 4];
            float4 a1 = *(const float4*)&A[((tmB + 1) * 4 + ks) * 128 + lane * 4];
            #pragma unroll
            for (int nt = 0; nt < 8; nt++) {
                float2 bv = *(const float2*)&B[((tnB + nt) * 4 + ks) * 64 + lane * 2];
                mma_tf32(acc[0][nt], a0.x, a0.y, a0.z, a0.w, bv.x, bv.y);
                mma_tf32(acc[1][nt], a1.x, a1.y, a1.z, a1.w, bv.x, bv.y);
            }
        }
        __syncthreads();
    }

    #pragma unroll
    for (int mt = 0; mt < 2; mt++)
    #pragma unroll
    for (int i = 0; i < 2; i++) {
        int m = m0t * 16 + (tmB + mt) * 16 + g + i * 8;
        int bb2 = m >> 12, ns = m & (NSEQ - 1);
        #pragma unroll
        for (int nt = 0; nt < 8; nt++) {
            int c = n0t * 8 + (tnB + nt) * 8 + tig * 2;
            int h = c >> 6, dh = c & 63;
            float v0 = f2tf(acc[mt][nt][i * 2]), v1 = f2tf(acc[mt][nt][i * 2 + 1]);
            long bhb = (long)(bb2 * HEADS + h);
            if (blockIdx.z == 0) {
                // packed-A per bh: nkt=8 (k=64)
                int q = ((ns >> 4) * 8 + (dh >> 3)) * 32 + (ns & 7) * 4 + (dh & 3);
                int e = ((ns >> 3) & 1) + 2 * ((dh >> 2) & 1);
                float* Qp = g_Q + bhb * (NSEQ * DH);
                Qp[q * 4 + e] = v0;
                Qp[q * 4 + e + 4] = v1;
            } else {
                float* outp = (blockIdx.z == 1) ? g_K : g_V;
                *(float2*)&outp[(bhb * NSEQ + ns) * DH + dh] = make_float2(v0, v1);
            }
        }
    }
}

// =====================================================================
// proj: KP[r,d] = sum_n E[n,r] K[n,d].  A packed (E/F); B raw pre-tf32.
// KP written packed-B (n=r,k=d); VP written packed-B (n=d,k=r).  Pre-tf32.
// =====================================================================
#define PSTG (4096 + 32*72)
#define PRJ_SMEM (3*PSTG*4)

__global__ __launch_bounds__(256, 2) void proj_kernel()
{
    extern __shared__ float sm[];
    const int bh = blockIdx.y, h = bh & 7;
    const int r0t = blockIdx.x * 8;
    const float* Ap = (blockIdx.z == 0 ? g_Ep : g_Fp) + (long)h * RP * NSEQ;
    const float* S  = (blockIdx.z == 0 ? g_K : g_V) + (long)bh * NSEQ * DH;
    float* D = (blockIdx.z == 0 ? g_KP : g_VP) + bh * RP * DH;

    const int tid = threadIdx.x, wid = tid >> 5, lane = tid & 31;
    const int g = lane >> 2, tig = lane & 3;
    const int tmB = (wid >> 1) * 2, wn = (wid & 1) * 32;

    float acc[2][4][4] = {};

    auto load = [&](int s) {
        float* buf = sm + (s % 3) * PSTG;
        uint32_t ab = s2u(buf), bb = s2u(buf + 4096);
        #pragma unroll
        for (int l = 0; l < 4; l++) {
            int q = l * 256 + tid, tl = q >> 7, r = q & 127;
            cpa16(ab + (tl * 512 + r * 4) * 4, &Ap[(long)(r0t + tl) * 65536 + s * 512 + r * 4]);
        }
        #pragma unroll
        for (int l = 0; l < 2; l++) {
            int rr = l * 16 + (tid >> 4), c4 = (tid & 15) * 4;
            cpa16(bb + (rr * 72 + c4) * 4, &S[(long)(s * 32 + rr) * DH + c4]);
        }
        cpcommit();
    };

    load(0); load(1);
    for (int s = 0; s < 128; s++) {
        if (s + 2 < 128) { load(s + 2); cpwait<2>(); }
        else if (s + 1 < 128) { cpwait<1>(); }
        else { cpwait<0>(); }
        __syncthreads();

        const float* A = sm + (s % 3) * PSTG;
        const float* B = A + 4096;
        #pragma unroll
        for (int ks = 0; ks < 4; ks++) {
            int kb = ks * 8;
            float4 a0 = *(const float4*)&A[((tmB    ) * 4 + ks) * 128 + lane * 4];
            float4 a1 = *(const float4*)&A[((tmB + 1) * 4 + ks) * 128 + lane * 4];
            #pragma unroll
            for (int nt = 0; nt < 4; nt++) {
                float b0 = B[(kb + tig)     * 72 + wn + nt * 8 + g];
                float b1 = B[(kb + tig + 4) * 72 + wn + nt * 8 + g];
                mma_tf32(acc[0][nt], a0.x, a0.y, a0.z, a0.w, b0, b1);
                mma_tf32(acc[1][nt], a1.x, a1.y, a1.z, a1.w, b0, b1);
            }
        }
        __syncthreads();
    }

    #pragma unroll
    for (int mt = 0; mt < 2; mt++)
    #pragma unroll
    for (int i = 0; i < 2; i++) {
        int r = r0t * 16 + (tmB + mt) * 16 + g + i * 8;
        #pragma unroll
        for (int nt = 0; nt < 4; nt++) {
            int c = wn + nt * 8 + tig * 2;
            float v0 = f2tf(acc[mt][nt][i * 2]), v1 = f2tf(acc[mt][nt][i * 2 + 1]);
            if (blockIdx.z == 0) {
                // KP packed-B: n=r (nkt=8 over d)
                int q = ((r >> 3) * 8 + (c >> 3)) * 32 + (r & 7) * 4 + (c & 3);
                int e = (c >> 2) & 1;
                D[q * 2 + e] = v0;
                D[(q + 1) * 2 + e] = v1;
            } else {
                // VP packed-B: n=d (nkt=32 over r)
                int q = ((c >> 3) * 32 + (r >> 3)) * 32 + (c & 7) * 4 + (r & 3);
                int e = (r >> 2) & 1;
                D[q * 2 + e] = v0;
                D[q * 2 + e + 8] = v1;   // c+1 -> q+4 -> +8 floats
            }
        }
    }
}

// =====================================================================
// attn: packed-fragment Q/KP/VP (pure copy staging); Ps path unchanged.
// grid (16, 64), 4 chunks of 64 Q rows per block.
// =====================================================================
#define AT_QS 4096
#define AT_KP 16384
#define AT_VP 16384
#define AT_PS (64*260)
#define AT_SMEM ((AT_QS + AT_KP + AT_VP + AT_PS + 256)*4)

__global__ __launch_bounds__(256) void attn_kernel()
{
    extern __shared__ float sm[];
    float* Qs   = sm;                 // packed-A, 4 tm x 8 tk x 128
    float* kps  = Qs + AT_QS;         // packed-B, 32 tn x 8 tk x 64
    float* vps  = kps + AT_KP;        // packed-B, 8 tn x 32 tk x 64
    float* Ps   = vps + AT_VP;        // [64][260]
    float* redM = Ps + AT_PS;
    float* redS = redM + 128;

    const int bh = blockIdx.y;
    const int tid = threadIdx.x;
    const int wid = tid >> 5, lane = tid & 31, g = lane >> 2, tig = lane & 3;
    const int wm = (wid >> 1) * 16, wn = wid & 1;
    const int tmq = wid >> 1;

    {
        const float* kpP = g_KP + (long)bh * RP * DH;
        const float* vpP = g_VP + (long)bh * RP * DH;
        #pragma unroll
        for (int l = 0; l < 16; l++) {
            int idx = (l * 256 + tid) * 4;
            *(float4*)&kps[idx] = *(const float4*)&kpP[idx];
            *(float4*)&vps[idx] = *(const float4*)&vpP[idx];
        }
    }

    const int b = bh >> 3, h = bh & 7;
    const float scale = 0.125f;

    for (int ci = 0; ci < 4; ci++) {
        const int n0 = blockIdx.x * 256 + ci * 64;
        const float* Qp = g_Q + (long)bh * (NSEQ * DH) + (n0 >> 4) * 1024;

        __syncthreads();
        #pragma unroll
        for (int l = 0; l < 4; l++) {
            int idx = (l * 256 + tid) * 4;
            *(float4*)&Qs[idx] = *(const float4*)&Qp[idx];
        }
        __syncthreads();

        // ---- phase 1: S = Q @ kp^T ----
        float acc[16][4] = {};
        #pragma unroll
        for (int ks = 0; ks < 8; ks++) {
            float4 av = *(const float4*)&Qs[(tmq * 8 + ks) * 128 + lane * 4];
            #pragma unroll
            for (int nt = 0; nt < 16; nt++) {
                float2 bv = *(const float2*)&kps[((wn * 16 + nt) * 8 + ks) * 64 + lane * 2];
                mma_tf32(acc[nt], av.x, av.y, av.z, av.w, bv.x, bv.y);
            }
        }

        const int r0 = wm + g, r1 = r0 + 8;
        float mx0 = -1e30f, mx1 = -1e30f;
        #pragma unroll
        for (int nt = 0; nt < 16; nt++) {
            mx0 = fmaxf(mx0, fmaxf(acc[nt][0], acc[nt][1]));
            mx1 = fmaxf(mx1, fmaxf(acc[nt][2], acc[nt][3]));
        }
        mx0 = fmaxf(mx0, __shfl_xor_sync(0xffffffffu, mx0, 1));
        mx0 = fmaxf(mx0, __shfl_xor_sync(0xffffffffu, mx0, 2));
        mx1 = fmaxf(mx1, __shfl_xor_sync(0xffffffffu, mx1, 1));
        mx1 = fmaxf(mx1, __shfl_xor_sync(0xffffffffu, mx1, 2));
        if (tig == 0) { redM[r0 * 2 + wn] = mx0; redM[r1 * 2 + wn] = mx1; }
        __syncthreads();
        mx0 = fmaxf(redM[r0 * 2], redM[r0 * 2 + 1]) * scale;
        mx1 = fmaxf(redM[r1 * 2], redM[r1 * 2 + 1]) * scale;

        float s0 = 0.f, s1 = 0.f;
        #pragma unroll
        for (int nt = 0; nt < 16; nt++) {
            int c = wn * 128 + nt * 8 + tig * 2;
            float e0 = __expf(acc[nt][0] * scale - mx0);
            float e1 = __expf(acc[nt][1] * scale - mx0);
            s0 += e0 + e1;
            *(float2*)&Ps[r0 * 260 + c] = make_float2(f2tf(e0), f2tf(e1));
            float e2 = __expf(acc[nt][2] * scale - mx1);
            float e3 = __expf(acc[nt][3] * scale - mx1);
            s1 += e2 + e3;
            *(float2*)&Ps[r1 * 260 + c] = make_float2(f2tf(e2), f2tf(e3));
        }
        s0 += __shfl_xor_sync(0xffffffffu, s0, 1);
        s0 += __shfl_xor_sync(0xffffffffu, s0, 2);
        s1 += __shfl_xor_sync(0xffffffffu, s1, 1);
        s1 += __shfl_xor_sync(0xffffffffu, s1, 2);
        if (tig == 0) { redS[r0 * 2 + wn] = s0; redS[r1 * 2 + wn] = s1; }
        __syncthreads();

        // ---- phase 2: O = P @ vp ----
        float acc2[4][4] = {};
        #pragma unroll 8
        for (int ks = 0; ks < 32; ks++) {
            int kb = ks * 8;
            float a0 = Ps[(wm + g)     * 260 + kb + tig];
            float a1 = Ps[(wm + g + 8) * 260 + kb + tig];
            float a2 = Ps[(wm + g)     * 260 + kb + tig + 4];
            float a3 = Ps[(wm + g + 8) * 260 + kb + tig + 4];
            #pragma unroll
            for (int nt = 0; nt < 4; nt++) {
                float2 bv = *(const float2*)&vps[((wn * 4 + nt) * 32 + ks) * 64 + lane * 2];
                mma_tf32(acc2[nt], a0, a1, a2, a3, bv.x, bv.y);
            }
        }

        const float inv0 = __frcp_rn(redS[r0 * 2] + redS[r0 * 2 + 1]);
        const float inv1 = __frcp_rn(redS[r1 * 2] + redS[r1 * 2 + 1]);
        float* ao = g_AO + (long)(b * NSEQ + n0) * DM + h * DH;
        #pragma unroll
        for (int nt = 0; nt < 4; nt++) {
            int c = wn * 32 + nt * 8 + tig * 2;
            *(float2*)&ao[r0 * DM + c] =
                make_float2(f2tf(acc2[nt][0] * inv0), f2tf(acc2[nt][1] * inv0));
            *(float2*)&ao[r1 * DM + c] =
                make_float2(f2tf(acc2[nt][2] * inv1), f2tf(acc2[nt][3] * inv1));
        }
    }
}

// =====================================================================
// outproj: A raw pre-tf32 AO, B packed wo.
// =====================================================================
#define OA 4608
#define OSTG (OA + 4096)
#define OUT_SMEM (3*OSTG*4)

__global__ __launch_bounds__(256, 2) void outproj_kernel(
    const float* __restrict__ bo, float* __restrict__ out)
{
    extern __shared__ float sm[];
    const float* wsrc = g_wp + 3 * DM * DM;

    const int m0 = blockIdx.y * 128, n0t = blockIdx.x * 16;
    const int tid = threadIdx.x, wid = tid >> 5, lane = tid & 31;
    const int g = lane >> 2, tig = lane & 3;
    const int wm = (wid >> 1) * 32, tnB = (wid & 1) * 8;

    float acc[2][8][4] = {};

    auto load = [&](int s) {
        float* buf = sm + (s % 3) * OSTG;
        uint32_t ab = s2u(buf), bb = s2u(buf + OA);
        int k0 = s * 32;
        #pragma unroll
        for (int l = 0; l < 4; l++) {
            int r = l * 32 + (tid >> 3), c4 = (tid & 7) * 4;
            cpa16(ab + (r * 36 + c4) * 4, &g_AO[(long)(m0 + r) * DM + k0 + c4]);
        }
        #pragma unroll
        for (int l = 0; l < 4; l++) {
            int q = l * 256 + tid, tl = q >> 6, r = q & 63;
            cpa16(bb + (tl * 256 + r * 4) * 4, &wsrc[(long)(n0t + tl) * 4096 + s * 256 + r * 4]);
        }
        cpcommit();
    };

    load(0); load(1);
    for (int s = 0; s < 16; s++) {
        if (s + 2 < 16) { load(s + 2); cpwait<2>(); }
        else if (s + 1 < 16) { cpwait<1>(); }
        else { cpwait<0>(); }
        __syncthreads();

        const float* A = sm + (s % 3) * OSTG;
        const float* B = A + OA;
        #pragma unroll
        for (int ks = 0; ks < 4; ks++) {
            int kb = ks * 8;
            float a[2][4];
            #pragma unroll
            for (int mt = 0; mt < 2; mt++) {
                int r = wm + mt * 16;
                a[mt][0] = A[(r + g)     * 36 + kb + tig];
                a[mt][1] = A[(r + g + 8) * 36 + kb + tig];
                a[mt][2] = A[(r + g)     * 36 + kb + tig + 4];
                a[mt][3] = A[(r + g + 8) * 36 + kb + tig + 4];
            }
            #pragma unroll
            for (int nt = 0; nt < 8; nt++) {
                float2 bv = *(const float2*)&B[((tnB + nt) * 4 + ks) * 64 + lane * 2];
                mma_tf32(acc[0][nt], a[0][0], a[0][1], a[0][2], a[0][3], bv.x, bv.y);
                mma_tf32(acc[1][nt], a[1][0], a[1][1], a[1][2], a[1][3], bv.x, bv.y);
            }
        }
        __syncthreads();
    }

    #pragma unroll
    for (int mt = 0; mt < 2; mt++)
    #pragma unroll
    for (int i = 0; i < 2; i++) {
        int m = m0 + wm + mt * 16 + g + i * 8;
        #pragma unroll
        for (int nt = 0; nt < 8; nt++) {
            int c = n0t * 8 + (tnB + nt) * 8 + tig * 2;
            float2 bias = *(const float2*)&bo[c];
            *(float2*)&out[(long)m * DM + c] =
                make_float2(acc[mt][nt][i * 2] + bias.x, acc[mt][nt][i * 2 + 1] + bias.y);
        }
    }
}

// =====================================================================
extern "C" void kernel_launch(void* const* d_in, const int* in_sizes, int n_in,
                              void* d_out, int out_size)
{
    (void)in_sizes; (void)n_in; (void)out_size;
    const float* x  = (const float*)d_in[0];
    const float* wq = (const float*)d_in[1];
    const float* wk = (const float*)d_in[2];
    const float* wv = (const float*)d_in[3];
    const float* E  = (const float*)d_in[4];
    const float* F  = (const float*)d_in[5];
    const float* wo = (const float*)d_in[6];
    const float* bo = (const float*)d_in[7];
    float* out = (float*)d_out;

    cudaFuncSetAttribute(qkv_kernel,     cudaFuncAttributeMaxDynamicSharedMemorySize, QKV_SMEM);
    cudaFuncSetAttribute(proj_kernel,    cudaFuncAttributeMaxDynamicSharedMemorySize, PRJ_SMEM);
    cudaFuncSetAttribute(attn_kernel,    cudaFuncAttributeMaxDynamicSharedMemorySize, AT_SMEM);
    cudaFuncSetAttribute(outproj_kernel, cudaFuncAttributeMaxDynamicSharedMemorySize, OUT_SMEM);

    float *p_xp, *p_wp, *p_Ep, *p_Fp;
    cudaGetSymbolAddress((void**)&p_xp, g_xp);
    cudaGetSymbolAddress((void**)&p_wp, g_wp);
    cudaGetSymbolAddress((void**)&p_Ep, g_Ep);
    cudaGetSymbolAddress((void**)&p_Fp, g_Fp);

    pack_a<<<MTOT*DM/1024, 256>>>(x, p_xp, 64, DM, 1, 0, 0);
    pack_a<<<dim3(RP*NSEQ/1024, HEADS), 256>>>(E, p_Ep, 512, 1, RP,
                                               (long)NSEQ*RP, (long)RP*NSEQ);
    pack_a<<<dim3(RP*NSEQ/1024, HEADS), 256>>>(F, p_Fp, 512, 1, RP,
                                               (long)NSEQ*RP, (long)RP*NSEQ);
    pack_b<<<DM*DM/512, 256>>>(wq, p_wp,            64, DM);
    pack_b<<<DM*DM/512, 256>>>(wk, p_wp + DM*DM,    64, DM);
    pack_b<<<DM*DM/512, 256>>>(wv, p_wp + 2*DM*DM,  64, DM);
    pack_b<<<DM*DM/512, 256>>>(wo, p_wp + 3*DM*DM,  64, DM);

    qkv_kernel    <<<dim3(4, 256, 3), 256, QKV_SMEM>>>();
    proj_kernel   <<<dim3(2, 64, 2),  256, PRJ_SMEM>>>();
    attn_kernel   <<<dim3(16, 64),    256, AT_SMEM>>>();
    outproj_kernel<<<dim3(4, 256),    256, OUT_SMEM>>>(bo, out);
}